// round 13
// baseline (speedup 1.0000x reference)
#include <cuda_runtime.h>

#define B 64
#define H 768
#define E 128

#define NRED 256                 // core-reduce blocks (32 KB each), bids [0,256)
#define NGEMM 64                 // full-K GEMM blocks (8b x 16e), bids [256,320)
#define GRID (NRED + NGEMM)      // 320

__device__ float g_S2p[NRED];    // core partials (2 per leading index i)
__device__ unsigned g_arrive;    // reduce-arrive counter; self-resetting
__device__ unsigned g_done2;     // gemm-passed-spin counter; self-resetting

__device__ __forceinline__ float dot4(float4 a, float4 b) {
    return a.x * b.x + a.y * b.y + a.z * b.z + a.w * b.w;
}

__global__ void __launch_bounds__(256)
k_all(const float* __restrict__ core,
      const float* __restrict__ hs, const float* __restrict__ rs,
      const float* __restrict__ ts, const float* __restrict__ we,
      const float* __restrict__ wr, const float* __restrict__ be,
      const float* __restrict__ br, float* __restrict__ out) {
    __shared__ float4 s_src[3][8][17];   // [mat][b][k4+swizzle]   6.5 KB
    __shared__ float4 s_w[2][16][17];    // [We/Wr][e][k4]         8.7 KB

    const int bid = blockIdx.x;
    const int tid = threadIdx.x;

    if (bid < NRED) {
        // ------- core reduction: 32 KB chunk, 8 explicit loads (MLP=8) ------
        if (bid == 0 && tid < B) out[tid] = 0.f;   // zero out before arriving

        const float4* src = reinterpret_cast<const float4*>(core) + (size_t)bid * 2048;
        const float4 v0 = __ldg(src + tid);
        const float4 v1 = __ldg(src + tid + 256);
        const float4 v2 = __ldg(src + tid + 512);
        const float4 v3 = __ldg(src + tid + 768);
        const float4 v4 = __ldg(src + tid + 1024);
        const float4 v5 = __ldg(src + tid + 1280);
        const float4 v6 = __ldg(src + tid + 1536);
        const float4 v7 = __ldg(src + tid + 1792);
        float s = ((((v0.x + v0.y) + (v0.z + v0.w)) + ((v1.x + v1.y) + (v1.z + v1.w)))
                +  (((v2.x + v2.y) + (v2.z + v2.w)) + ((v3.x + v3.y) + (v3.z + v3.w))))
                + ((((v4.x + v4.y) + (v4.z + v4.w)) + ((v5.x + v5.y) + (v5.z + v5.w)))
                +  (((v6.x + v6.y) + (v6.z + v6.w)) + ((v7.x + v7.y) + (v7.z + v7.w))));
#pragma unroll
        for (int o = 16; o > 0; o >>= 1) s += __shfl_xor_sync(0xffffffffu, s, o);
        float* ws = reinterpret_cast<float*>(s_w);
        if ((tid & 31) == 0) ws[tid >> 5] = s;
        __syncthreads();
        if (tid == 0) {
            float tot = 0.f;
#pragma unroll
            for (int w = 0; w < 8; w++) tot += ws[w];
            g_S2p[bid] = tot;
            __threadfence();             // publish g_S2p (and block0's zeros)
            atomicAdd(&g_arrive, 1u);
        }
        return;                          // reduce blocks never wait
    }

    // ------- full-K triple GEMM: 8b x 16e x 768k, accumulate in registers ---
    const int gb = bid - NRED;           // 0..63
    const int ec = gb & 7, bg = gb >> 3;
    const int b0 = bg * 8, e0 = ec * 16;

    const int te = tid & 15;             // e within tile
    const int tb = (tid >> 4) & 7;       // b within tile
    const int kh = tid >> 7;             // K half (0: k4 0..7, 1: k4 8..15)

    const float4* g0 = reinterpret_cast<const float4*>(hs);
    const float4* g1 = reinterpret_cast<const float4*>(rs);
    const float4* g2 = reinterpret_cast<const float4*>(ts);
    const float4* gwe = reinterpret_cast<const float4*>(we);
    const float4* gwr = reinterpret_cast<const float4*>(wr);

    float h = 0.f, r = 0.f, t = 0.f;

#pragma unroll 1
    for (int st = 0; st < 12; st++) {
        const int c0 = st * 16;
        __syncthreads();                 // previous-stage reads complete
        // load: src 3*8*16 = 384 f4, w 2*16*16 = 512 f4 -> 896 entries
        for (int i = tid; i < 896; i += 256) {
            if (i < 384) {
                const int m = i >> 7, rem = i & 127;
                const int row = rem >> 4, c4 = rem & 15;
                const size_t gidx = (size_t)(b0 + row) * 192 + c0 + c4;
                const float4 v = (m == 0) ? g0[gidx] : (m == 1) ? g1[gidx] : g2[gidx];
                s_src[m][row][c4 ^ (row & 7)] = v;
            } else {
                const int j = i - 384;
                const int m = j >> 8, rem = j & 255;
                const int row = rem >> 4, c4 = rem & 15;
                const size_t gidx = (size_t)(e0 + row) * 192 + c0 + c4;
                s_w[m][row][c4 ^ (row & 7)] = m ? gwr[gidx] : gwe[gidx];
            }
        }
        __syncthreads();

        const int kb = kh * 8;
#pragma unroll
        for (int k = 0; k < 8; k++) {
            const int k4 = kb + k;
            const float4 vwe = s_w[0][te][k4 ^ (te & 7)];
            const float4 vwr = s_w[1][te][k4 ^ (te & 7)];
            const float4 ah = s_src[0][tb][k4 ^ (tb & 7)];
            const float4 ar = s_src[1][tb][k4 ^ (tb & 7)];
            const float4 at = s_src[2][tb][k4 ^ (tb & 7)];
            h += dot4(vwe, ah);
            r += dot4(vwr, ar);
            t += dot4(vwe, at);
        }
    }

    // ------- merge K halves via smem ---------------------------------------
    __syncthreads();
    float* sh = reinterpret_cast<float*>(s_src);   // 3*128 floats scratch
    if (kh == 1) {
        const int idx = tb * 16 + te;
        sh[idx] = h; sh[128 + idx] = r; sh[256 + idx] = t;
    }
    // wait for all reduce blocks (S2 ready); overlaps with the merge sync
    if (tid == 0) {
        volatile unsigned* p = &g_arrive;
        while (*p < NRED) __nanosleep(16);
        __threadfence();
    }
    __syncthreads();

    // ------- fold: partial energy for this block's (8b x 16e) tile ---------
    if (kh == 0) {
        const int idx = tb * 16 + te;
        h += sh[idx]; r += sh[128 + idx]; t += sh[256 + idx];
        const int e = e0 + te;
        const float s2 = g_S2p[2 * e] + g_S2p[2 * e + 1];
        float v = (h + be[e]) * (r + br[e]) * (t + be[e]) * s2;
#pragma unroll
        for (int o = 8; o > 0; o >>= 1) v += __shfl_xor_sync(0xffffffffu, v, o);
        if (te == 0) atomicAdd(&out[b0 + tb], -v);
    }
    __syncthreads();

    // ------- counter reset (deadlock-safe: done2 counted after spin) -------
    if (tid == 0) {
        const unsigned d = atomicAdd(&g_done2, 1u);
        if (d == NGEMM - 1) {            // last GEMM block past the spin
            g_arrive = 0u;
            __threadfence();
            g_done2 = 0u;
        }
    }
}

// ---------------------------------------------------------------------------
extern "C" void kernel_launch(void* const* d_in, const int* in_sizes, int n_in,
                              void* d_out, int out_size) {
    const float* head = (const float*)d_in[0];
    const float* rel  = (const float*)d_in[1];
    const float* tail = (const float*)d_in[2];
    const float* We   = (const float*)d_in[3];
    const float* be   = (const float*)d_in[4];
    const float* Wr   = (const float*)d_in[5];
    const float* br   = (const float*)d_in[6];
    const float* core = (const float*)d_in[7];
    float* out = (float*)d_out;

    k_all<<<GRID, 256>>>(core, head, rel, tail, We, Wr, be, br, out);
}

// round 14
// speedup vs baseline: 3.3582x; 3.3582x over previous
#include <cuda_runtime.h>

#define B 64
#define H 768
#define E 128

#define NRED 256    // core-reduce blocks (32 KB each), bids [0,256)
#define KS 12       // GEMM k-splits
#define NGEMM 192   // 12 ks x 8 echunk x 2 bgroup, bids [256,448)
#define GRID (NRED + NGEMM)

__device__ float g_S2p[NRED];          // core partials (2 per leading index i)
__device__ float g_P[3][KS][B][E];     // [mat][ks][b][e] gemm partials

// ---------------------------------------------------------------------------
// Kernel A (measured best, unchanged): blocks [0,256) reduce core (MLP=8);
// blocks [256,448) triple GEMM 32b x 16e x 64k.
// ---------------------------------------------------------------------------
__global__ void k_fused(const float* __restrict__ core,
                        const float* __restrict__ hs, const float* __restrict__ rs,
                        const float* __restrict__ ts, const float* __restrict__ we,
                        const float* __restrict__ wr) {
    __shared__ float4 s_src[3][32][18];  // gemm src tiles (swizzled)
    __shared__ float4 s_w[2][16][18];    // gemm We/Wr tiles

    const int bid = blockIdx.x;
    const int tid = threadIdx.x;

    if (bid < NRED) {
        const float4* src = reinterpret_cast<const float4*>(core) + (size_t)bid * 2048;
        const float4 v0 = __ldg(src + tid);
        const float4 v1 = __ldg(src + tid + 256);
        const float4 v2 = __ldg(src + tid + 512);
        const float4 v3 = __ldg(src + tid + 768);
        const float4 v4 = __ldg(src + tid + 1024);
        const float4 v5 = __ldg(src + tid + 1280);
        const float4 v6 = __ldg(src + tid + 1536);
        const float4 v7 = __ldg(src + tid + 1792);
        float s = ((((v0.x + v0.y) + (v0.z + v0.w)) + ((v1.x + v1.y) + (v1.z + v1.w)))
                +  (((v2.x + v2.y) + (v2.z + v2.w)) + ((v3.x + v3.y) + (v3.z + v3.w))))
                + ((((v4.x + v4.y) + (v4.z + v4.w)) + ((v5.x + v5.y) + (v5.z + v5.w)))
                +  (((v6.x + v6.y) + (v6.z + v6.w)) + ((v7.x + v7.y) + (v7.z + v7.w))));
#pragma unroll
        for (int o = 16; o > 0; o >>= 1) s += __shfl_xor_sync(0xffffffffu, s, o);
        float* ws = reinterpret_cast<float*>(s_w);
        if ((tid & 31) == 0) ws[tid >> 5] = s;
        __syncthreads();
        if (tid == 0) {
            float tot = 0.f;
#pragma unroll
            for (int w = 0; w < 8; w++) tot += ws[w];
            g_S2p[bid] = tot;
        }
        return;
    }

    const int lin = bid - NRED;
    const int ks = lin % KS, ec = (lin / KS) & 7, bg = lin / (KS * 8);
    const int b0 = bg * 32, e0 = ec * 16;
    const int c0 = ks * 16;

    const float4* g0 = reinterpret_cast<const float4*>(hs);
    const float4* g1 = reinterpret_cast<const float4*>(rs);
    const float4* g2 = reinterpret_cast<const float4*>(ts);
#pragma unroll
    for (int i = tid; i < 512; i += 256) {
        const int row = i >> 4, c4 = i & 15;
        const size_t gidx = (size_t)(b0 + row) * 192 + c0 + c4;
        const int sc = c4 ^ (row & 7);
        s_src[0][row][sc] = g0[gidx];
        s_src[1][row][sc] = g1[gidx];
        s_src[2][row][sc] = g2[gidx];
    }
    {
        const int row = tid >> 4, c4 = tid & 15;
        const size_t gidx = (size_t)(e0 + row) * 192 + c0 + c4;
        const int sc = c4 ^ (row & 7);
        s_w[0][row][sc] = reinterpret_cast<const float4*>(we)[gidx];
        s_w[1][row][sc] = reinterpret_cast<const float4*>(wr)[gidx];
    }
    __syncthreads();

    const int te = tid & 15;
    const int tb = tid >> 4;
    const int ba = 2 * tb, bb = ba + 1;

    float h0 = 0.f, h1 = 0.f, r0 = 0.f, r1 = 0.f, t0 = 0.f, t1 = 0.f;
#pragma unroll
    for (int k4 = 0; k4 < 16; k4++) {
        const float4 vwe = s_w[0][te][k4 ^ (te & 7)];
        const float4 vwr = s_w[1][te][k4 ^ (te & 7)];
        const int sa = k4 ^ (ba & 7), sb = k4 ^ (bb & 7);
        float4 a, c;
        a = s_src[0][ba][sa]; c = s_src[0][bb][sb];
        h0 += vwe.x * a.x + vwe.y * a.y + vwe.z * a.z + vwe.w * a.w;
        h1 += vwe.x * c.x + vwe.y * c.y + vwe.z * c.z + vwe.w * c.w;
        a = s_src[1][ba][sa]; c = s_src[1][bb][sb];
        r0 += vwr.x * a.x + vwr.y * a.y + vwr.z * a.z + vwr.w * a.w;
        r1 += vwr.x * c.x + vwr.y * c.y + vwr.z * c.z + vwr.w * c.w;
        a = s_src[2][ba][sa]; c = s_src[2][bb][sb];
        t0 += vwe.x * a.x + vwe.y * a.y + vwe.z * a.z + vwe.w * a.w;
        t1 += vwe.x * c.x + vwe.y * c.y + vwe.z * c.z + vwe.w * c.w;
    }

    const int bga = b0 + ba, bgb = b0 + bb;
    const int e = e0 + te;
    g_P[0][ks][bga][e] = h0;  g_P[0][ks][bgb][e] = h1;
    g_P[1][ks][bga][e] = r0;  g_P[1][ks][bgb][e] = r1;
    g_P[2][ks][bga][e] = t0;  g_P[2][ks][bgb][e] = t1;
}

// ---------------------------------------------------------------------------
// Kernel B (rewritten for ONE exposed L2 round-trip):
// 64 blocks (one per b) x 384 threads = (3 mats x 4 ks-quarters x 32 e-quads).
// Phase 1: every thread issues 3 independent float4 loads (36 ks-loads per
//          (m,e-quad) in flight chip-wide); threads 0..31 prefetch be/br/S2p
//          into smem inside the same latency window.
// Phase 2: 96 threads fold ks-quarters in smem.
// Phase 3: one warp computes the triple product and reduces.
// ---------------------------------------------------------------------------
__global__ void k_combine(const float* __restrict__ be, const float* __restrict__ br,
                          float* __restrict__ out) {
    __shared__ float4 s1[3][4][32];   // [m][kq][e4] partial sums
    __shared__ float4 sbias[2][32];   // be, br as float4 per e-quad
    __shared__ float4 ss2[32];        // S2[e] (pair-summed) per e-quad

    const int b = blockIdx.x;
    const int tid = threadIdx.x;           // 0..383
    const int m = tid >> 7;                // matrix 0/1/2
    const int rem = tid & 127;
    const int kq = rem >> 5;               // ks quarter 0..3
    const int e4 = rem & 31;               // e-quad 0..31

    // Phase 1: 3 independent float4 loads per thread (+ prefetch on tid<32)
    const float4* p0 = reinterpret_cast<const float4*>(&g_P[m][kq * 3 + 0][b][0]) + e4;
    const float4* p1 = reinterpret_cast<const float4*>(&g_P[m][kq * 3 + 1][b][0]) + e4;
    const float4* p2 = reinterpret_cast<const float4*>(&g_P[m][kq * 3 + 2][b][0]) + e4;
    const float4 a0 = __ldg(p0);
    const float4 a1 = __ldg(p1);
    const float4 a2 = __ldg(p2);

    if (tid < 32) {
        const float4 vb = __ldg(reinterpret_cast<const float4*>(be) + tid);
        const float4 vr = __ldg(reinterpret_cast<const float4*>(br) + tid);
        const float4 u0 = __ldg(reinterpret_cast<const float4*>(g_S2p) + 2 * tid);
        const float4 u1 = __ldg(reinterpret_cast<const float4*>(g_S2p) + 2 * tid + 1);
        sbias[0][tid] = vb;
        sbias[1][tid] = vr;
        ss2[tid] = make_float4(u0.x + u0.y, u0.z + u0.w, u1.x + u1.y, u1.z + u1.w);
    }

    float4 acc;
    acc.x = a0.x + a1.x + a2.x;
    acc.y = a0.y + a1.y + a2.y;
    acc.z = a0.z + a1.z + a2.z;
    acc.w = a0.w + a1.w + a2.w;
    s1[m][kq][e4] = acc;
    __syncthreads();

    // Phase 2: fold the 4 ks-quarters (96 threads)
    if (tid < 96) {
        const int m2 = tid >> 5, e42 = tid & 31;
        const float4 q0 = s1[m2][0][e42], q1 = s1[m2][1][e42];
        const float4 q2 = s1[m2][2][e42], q3 = s1[m2][3][e42];
        float4 f;
        f.x = (q0.x + q1.x) + (q2.x + q3.x);
        f.y = (q0.y + q1.y) + (q2.y + q3.y);
        f.z = (q0.z + q1.z) + (q2.z + q3.z);
        f.w = (q0.w + q1.w) + (q2.w + q3.w);
        s1[m2][0][e42] = f;
    }
    __syncthreads();

    // Phase 3: triple product + reduce (one warp)
    if (tid < 32) {
        const float4 h4 = s1[0][0][tid];
        const float4 r4 = s1[1][0][tid];
        const float4 t4 = s1[2][0][tid];
        const float4 vb = sbias[0][tid];
        const float4 vr = sbias[1][tid];
        const float4 s2 = ss2[tid];
        float v = (h4.x + vb.x) * (r4.x + vr.x) * (t4.x + vb.x) * s2.x
                + (h4.y + vb.y) * (r4.y + vr.y) * (t4.y + vb.y) * s2.y
                + (h4.z + vb.z) * (r4.z + vr.z) * (t4.z + vb.z) * s2.z
                + (h4.w + vb.w) * (r4.w + vr.w) * (t4.w + vb.w) * s2.w;
#pragma unroll
        for (int o = 16; o > 0; o >>= 1) v += __shfl_xor_sync(0xffffffffu, v, o);
        if (tid == 0) out[b] = -v;
    }
}

// ---------------------------------------------------------------------------
extern "C" void kernel_launch(void* const* d_in, const int* in_sizes, int n_in,
                              void* d_out, int out_size) {
    const float* head = (const float*)d_in[0];
    const float* rel  = (const float*)d_in[1];
    const float* tail = (const float*)d_in[2];
    const float* We   = (const float*)d_in[3];
    const float* be   = (const float*)d_in[4];
    const float* Wr   = (const float*)d_in[5];
    const float* br   = (const float*)d_in[6];
    const float* core = (const float*)d_in[7];
    float* out = (float*)d_out;

    k_fused<<<GRID, 256>>>(core, head, rel, tail, We, Wr);
    k_combine<<<B, 384>>>(be, br, out);
}